// round 7
// baseline (speedup 1.0000x reference)
#include <cuda_runtime.h>
#include <cuda_bf16.h>
#include <math.h>
#include <stdint.h>

// Problem constants (fixed shapes)
#define T_STEPS 2048
#define BATCH   256
#define HID     256
#define OUT_DIM 16

// Scratch (device globals: allocation-free kernel_launch)
__device__ float g_xp[134217728];          // [T][B][H] fp32, 512 MB
__device__ float g_hfinal[BATCH * HID];
__device__ __nv_bfloat16 g_xhi[134217728]; // x hi split, 256 MB
__device__ __nv_bfloat16 g_xlo[134217728]; // x lo split, 256 MB
__device__ __nv_bfloat16 g_WThi[65536];    // W_ih^T hi: [n][k]
__device__ __nv_bfloat16 g_WTlo[65536];    // W_ih^T lo: [n][k]

// ---------------------------------------------------------------------------
// helpers
// ---------------------------------------------------------------------------
__device__ __forceinline__ uint32_t smem_u32(const void* p) {
    uint32_t a;
    asm("{ .reg .u64 t; cvta.to.shared.u64 t, %1; cvt.u32.u64 %0, t; }"
        : "=r"(a) : "l"(p));
    return a;
}
__device__ __forceinline__ void cp16(uint32_t dst, const void* src) {
    asm volatile("cp.async.cg.shared.global [%0], [%1], 16;"
                 :: "r"(dst), "l"(src) : "memory");
}
__device__ __forceinline__ void ldsm_x4(uint32_t* r, uint32_t addr) {
    asm volatile("ldmatrix.sync.aligned.m8n8.x4.shared.b16 {%0,%1,%2,%3}, [%4];"
                 : "=r"(r[0]), "=r"(r[1]), "=r"(r[2]), "=r"(r[3]) : "r"(addr));
}
__device__ __forceinline__ void ldsm_x2(uint32_t* r, uint32_t addr) {
    asm volatile("ldmatrix.sync.aligned.m8n8.x2.shared.b16 {%0,%1}, [%2];"
                 : "=r"(r[0]), "=r"(r[1]) : "r"(addr));
}
__device__ __forceinline__ void mma_bf16(float* c, const uint32_t* a, const uint32_t* b) {
    asm volatile(
        "mma.sync.aligned.m16n8k16.row.col.f32.bf16.bf16.f32 "
        "{%0,%1,%2,%3}, {%4,%5,%6,%7}, {%8,%9}, {%0,%1,%2,%3};"
        : "+f"(c[0]), "+f"(c[1]), "+f"(c[2]), "+f"(c[3])
        : "r"(a[0]), "r"(a[1]), "r"(a[2]), "r"(a[3]), "r"(b[0]), "r"(b[1]));
}

// f32x2 helpers (recurrence)
__device__ __forceinline__ unsigned long long f32x2_pack(float x, float y) {
    unsigned long long r;
    asm("mov.b64 %0, {%1, %2};" : "=l"(r) : "r"(__float_as_uint(x)), "r"(__float_as_uint(y)));
    return r;
}
__device__ __forceinline__ void f32x2_unpack(unsigned long long v, float& x, float& y) {
    unsigned int lo, hi;
    asm("mov.b64 {%0, %1}, %2;" : "=r"(lo), "=r"(hi) : "l"(v));
    x = __uint_as_float(lo);
    y = __uint_as_float(hi);
}
__device__ __forceinline__ void ffma2(unsigned long long& acc,
                                      unsigned long long a, unsigned long long b) {
    asm("fma.rn.f32x2 %0, %1, %2, %0;" : "+l"(acc) : "l"(a), "l"(b));
}
__device__ __forceinline__ void fadd2(unsigned long long& acc, unsigned long long b) {
    asm("add.rn.f32x2 %0, %0, %1;" : "+l"(acc) : "l"(b));
}

// ---------------------------------------------------------------------------
// Kernel 0a: W_ih [k][n] -> transposed bf16 hi/lo [n][k]
// ---------------------------------------------------------------------------
__global__ __launch_bounds__(256)
void prep_w_kernel(const float* __restrict__ Wih) {
    int n = blockIdx.x;
    int k = threadIdx.x;
    float w = Wih[k * 256 + n];
    __nv_bfloat16 hi = __float2bfloat16(w);
    float lof = w - __bfloat162float(hi);
    g_WThi[n * 256 + k] = hi;
    g_WTlo[n * 256 + k] = __float2bfloat16(lof);
}

// ---------------------------------------------------------------------------
// Kernel 0b: x fp32 -> bf16 hi/lo splits (streaming)
// ---------------------------------------------------------------------------
__global__ __launch_bounds__(256)
void prep_x_kernel(const float* __restrict__ x) {
    size_t i = ((size_t)blockIdx.x * 256 + threadIdx.x) * 4;
    float4 f = *(const float4*)&x[i];
    __nv_bfloat162 h0 = __float22bfloat162_rn(make_float2(f.x, f.y));
    __nv_bfloat162 h1 = __float22bfloat162_rn(make_float2(f.z, f.w));
    float2 l0 = make_float2(f.x - __bfloat162float(h0.x), f.y - __bfloat162float(h0.y));
    float2 l1 = make_float2(f.z - __bfloat162float(h1.x), f.w - __bfloat162float(h1.y));
    __nv_bfloat162 lo0 = __float22bfloat162_rn(l0);
    __nv_bfloat162 lo1 = __float22bfloat162_rn(l1);
    uint2 hv, lv;
    hv.x = *(uint32_t*)&h0; hv.y = *(uint32_t*)&h1;
    lv.x = *(uint32_t*)&lo0; lv.y = *(uint32_t*)&lo1;
    *(uint2*)&g_xhi[i] = hv;
    *(uint2*)&g_xlo[i] = lv;
}

// ---------------------------------------------------------------------------
// Kernel 1: mma.sync bf16-split GEMM (unchanged from R5 passing version)
// ---------------------------------------------------------------------------
#define PADROW   40
#define AHI_OFF  0
#define ALO_OFF  10240
#define BHI_OFF  20480
#define BLO_OFF  40960
#define STAGE_B  61440
#define GSMEM    (2 * STAGE_B)

__global__ __launch_bounds__(512, 1)
void gemm_xp_mma_kernel(const float* __restrict__ bh) {
    extern __shared__ __align__(16) char dsm[];
    __shared__ float bias_s[256];

    const int tid = threadIdx.x;
    const int wid = tid >> 5;
    const int lid = tid & 31;
    const int wm  = wid & 1;
    const int wn  = wid >> 1;
    const uint32_t sb = smem_u32(dsm);

    if (tid < 256) bias_s[tid] = bh[tid];

    const size_t r0 = (size_t)blockIdx.x * 128;

    auto fill = [&](int s, int kt) {
        uint32_t base = sb + s * STAGE_B;
        {
            int c = tid;
            int row = c >> 2, q = c & 3;
            size_t ga = (r0 + row) * 256 + kt + q * 8;
            uint32_t d = base + row * (PADROW * 2) + q * 16;
            cp16(d + AHI_OFF, g_xhi + ga);
            cp16(d + ALO_OFF, g_xlo + ga);
        }
#pragma unroll
        for (int i = 0; i < 2; i++) {
            int c = tid + i * 512;
            int row = c >> 2, q = c & 3;
            size_t gb = (size_t)row * 256 + kt + q * 8;
            uint32_t d = base + row * (PADROW * 2) + q * 16;
            cp16(d + BHI_OFF, g_WThi + gb);
            cp16(d + BLO_OFF, g_WTlo + gb);
        }
    };

    float acc[4][4][4];
#pragma unroll
    for (int mi = 0; mi < 4; mi++)
#pragma unroll
        for (int ni = 0; ni < 4; ni++)
#pragma unroll
            for (int e = 0; e < 4; e++) acc[mi][ni][e] = 0.f;

    fill(0, 0);
    asm volatile("cp.async.commit_group;" ::: "memory");
    fill(1, 32);
    asm volatile("cp.async.commit_group;" ::: "memory");

    const int arow  = wm * 64 + (lid & 15);
    const int acolb = (lid >> 4) * 16;
    const int bnrow = wn * 32 + (lid & 7);
    const int bkoff = ((lid >> 3) & 1) * 16;

    for (int it = 0; it < 8; it++) {
        asm volatile("cp.async.wait_group 1;" ::: "memory");
        __syncthreads();

        uint32_t As = sb + (it & 1) * STAGE_B;
        uint32_t Bs = As + BHI_OFF;

#pragma unroll
        for (int k16 = 0; k16 < 2; k16++) {
            uint32_t ahi[4][4], alo[4][4];
#pragma unroll
            for (int mi = 0; mi < 4; mi++) {
                uint32_t a = As + (arow + mi * 16) * (PADROW * 2) + k16 * 32 + acolb;
                ldsm_x4(ahi[mi], a + AHI_OFF);
                ldsm_x4(alo[mi], a + ALO_OFF);
            }
#pragma unroll
            for (int ni = 0; ni < 4; ni++) {
                uint32_t bhi[2], blo[2];
                uint32_t ba = Bs + (bnrow + ni * 8) * (PADROW * 2) + k16 * 32 + bkoff;
                ldsm_x2(bhi, ba);
                ldsm_x2(blo, ba + (BLO_OFF - BHI_OFF));
#pragma unroll
                for (int mi = 0; mi < 4; mi++) {
                    mma_bf16(acc[mi][ni], ahi[mi], bhi);
                    mma_bf16(acc[mi][ni], alo[mi], bhi);
                    mma_bf16(acc[mi][ni], ahi[mi], blo);
                }
            }
        }
        __syncthreads();
        if (it + 2 < 8) fill(it & 1, (it + 2) * 32);
        asm volatile("cp.async.commit_group;" ::: "memory");
    }

#pragma unroll
    for (int mi = 0; mi < 4; mi++) {
#pragma unroll
        for (int ni = 0; ni < 4; ni++) {
            int m = wm * 64 + mi * 16 + (lid >> 2);
            int n = wn * 32 + ni * 8 + (lid & 3) * 2;
            float b0 = bias_s[n], b1 = bias_s[n + 1];
            {
                size_t r = r0 + m;
                int t = (int)(r & 2047), b = (int)(r >> 11);
                float2 v = make_float2(acc[mi][ni][0] + b0, acc[mi][ni][1] + b1);
                *(float2*)&g_xp[((size_t)t * BATCH + b) * HID + n] = v;
            }
            {
                size_t r = r0 + m + 8;
                int t = (int)(r & 2047), b = (int)(r >> 11);
                float2 v = make_float2(acc[mi][ni][2] + b0, acc[mi][ni][3] + b1);
                *(float2*)&g_xp[((size_t)t * BATCH + b) * HID + n] = v;
            }
        }
    }
}

// ---------------------------------------------------------------------------
// Kernel 2: K-split persistent recurrence.
// 128 CTAs x 512 threads; thread (j = tid>>1, half = tid&1) owns K rows
// [half*128, half*128+128) of W column j:
//   - 72 rows in registers (36 u64 k-pairs, loaded once from gmem)
//   - 56 rows in smem (14 quad groups per half)
// Partials for the two K-halves combine via shfl.xor lane pairs (same j).
// One __syncthreads per step. h buffers bank-skewed so the even/odd-lane
// broadcast pair shares a single wavefront.
//
// smem: W quads 28 groups * 4096 B = 114688; h: 2 bufs * 2080 B = 4160.
// ---------------------------------------------------------------------------
#define RREG   72                 // reg rows per half
#define RREGP  36                 // u64 pairs
#define RCH    18                 // 16B h-chunks covered by regs (72/4)
#define SCH    14                 // 16B h-chunks covered by smem (56/4)
#define WGRP   28                 // total smem quad groups (14 per half)
#define WSMB   (WGRP * 4096)      // 114688
#define HOFFB  WSMB
#define HBUFB  2080               // per ping-pong buffer (2 batches x 1040)
#define RSMEM  (WSMB + 2 * HBUFB) // 118848

__global__ __launch_bounds__(512, 1)
void rnn_recurrence_kernel(const float* __restrict__ W_hh) {
    extern __shared__ __align__(16) char sm[];

    const int tid  = threadIdx.x;
    const int j    = tid >> 1;
    const int half = tid & 1;
    const int b0   = blockIdx.x * 2;
    const int kbase = half * 128;

    // --- fill W smem quads: group g<14 -> rows 72+4g (half0),
    //     g>=14 -> rows 200+4(g-14) (half1); layout [g][j][4] ---
    for (int idx = tid; idx < WGRP * 256; idx += 512) {
        int g  = idx >> 8;
        int jj = idx & 255;
        int row = (g < 14) ? (72 + 4 * g) : (200 + 4 * (g - 14));
        float4 v;
        v.x = W_hh[(row + 0) * 256 + jj];
        v.y = W_hh[(row + 1) * 256 + jj];
        v.z = W_hh[(row + 2) * 256 + jj];
        v.w = W_hh[(row + 3) * 256 + jj];
        *(float4*)(sm + g * 4096 + jj * 16) = v;
    }

    // --- W register rows: [kbase, kbase+72) of column j as 36 u64 pairs ---
    unsigned long long wreg[RREGP];
#pragma unroll
    for (int r = 0; r < RREGP; r++)
        wreg[r] = f32x2_pack(W_hh[(kbase + 2 * r) * 256 + j],
                             W_hh[(kbase + 2 * r + 1) * 256 + j]);

    // --- zero h buffer 0: thread writes h[j] for batch = half ---
    *(float*)(sm + HOFFB + half * 1040 + (j >> 7) * 528 + (j & 127) * 4) = 0.f;
    __syncthreads();

    // xp for batch = half (this thread finishes that batch)
    const float* xpp = g_xp + (size_t)(b0 + half) * HID + j;
    float p = xpp[0];

    const char* wsm = sm + (half ? 14 * 4096 : 0) + j * 16;
    float hv = 0.f;

    for (int t = 0; t < T_STEPS; t++) {
        const char* hc = sm + HOFFB + (t & 1) * HBUFB + half * 528;
        const ulonglong2* H0 = (const ulonglong2*)hc;            // batch0, my seg
        const ulonglong2* H1 = (const ulonglong2*)(hc + 1040);   // batch1, my seg

        unsigned long long a0[2], a1[2];
        a0[0] = 0ull; a0[1] = 0ull; a1[0] = 0ull; a1[1] = 0ull;

        // prefetch next xp (hidden behind k-loop)
        int tn = (t + 1 < T_STEPS) ? (t + 1) : t;
        float pn = xpp[(size_t)tn * (BATCH * HID)];

        // register-W part: chunks 0..17 (k-local 0..72)
#pragma unroll
        for (int i = 0; i < RCH; i++) {
            ulonglong2 x0 = H0[i];
            ulonglong2 x1 = H1[i];
            ffma2(a0[0], x0.x, wreg[2 * i]);
            ffma2(a0[1], x0.y, wreg[2 * i + 1]);
            ffma2(a1[0], x1.x, wreg[2 * i]);
            ffma2(a1[1], x1.y, wreg[2 * i + 1]);
        }
        // smem-W part: chunks 18..31 (k-local 72..128)
#pragma unroll
        for (int i = 0; i < SCH; i++) {
            ulonglong2 w  = *(const ulonglong2*)(wsm + i * 4096);
            ulonglong2 x0 = H0[RCH + i];
            ulonglong2 x1 = H1[RCH + i];
            ffma2(a0[0], x0.x, w.x);
            ffma2(a0[1], x0.y, w.y);
            ffma2(a1[0], x1.x, w.x);
            ffma2(a1[1], x1.y, w.y);
        }

        fadd2(a0[0], a0[1]);
        fadd2(a1[0], a1[1]);
        float s0lo, s0hi, s1lo, s1hi;
        f32x2_unpack(a0[0], s0lo, s0hi);
        f32x2_unpack(a1[0], s1lo, s1hi);
        float f0 = s0lo + s0hi;          // my-half partial, batch0
        float f1 = s1lo + s1hi;          // my-half partial, batch1

        // combine K-halves: lane pairs (2m, 2m+1) share j
        float o0 = __shfl_xor_sync(0xffffffffu, f0, 1);
        float o1 = __shfl_xor_sync(0xffffffffu, f1, 1);
        float tot = half ? (f1 + o1) : (f0 + o0);
        hv = tanhf(tot + p);
        p = pn;

        // publish h[j] for batch = half into next buffer
        *(float*)(sm + HOFFB + ((t + 1) & 1) * HBUFB + half * 1040 +
                  (j >> 7) * 528 + (j & 127) * 4) = hv;
        __syncthreads();
    }

    g_hfinal[(size_t)(b0 + half) * HID + j] = hv;
}

// ---------------------------------------------------------------------------
// Kernel 3: classifier head (tiny)
// ---------------------------------------------------------------------------
__global__ __launch_bounds__(128)
void rnn_head_kernel(const float* __restrict__ fcw,
                     const float* __restrict__ fcb,
                     float* __restrict__ out) {
    __shared__ float hs[HID];
    __shared__ float part[8][OUT_DIM];
    const int b = blockIdx.x;
    const int tid = threadIdx.x;

    hs[tid]       = g_hfinal[(size_t)b * HID + tid];
    hs[tid + 128] = g_hfinal[(size_t)b * HID + tid + 128];
    __syncthreads();

    const int o   = tid & 15;
    const int seg = tid >> 4;
    float s = 0.f;
#pragma unroll
    for (int jj = 0; jj < 32; jj++) {
        int j = seg * 32 + jj;
        s += hs[j] * fcw[o * HID + j];
    }
    part[seg][o] = s;
    __syncthreads();
    if (tid < OUT_DIM) {
        float r = fcb[tid];
#pragma unroll
        for (int sg = 0; sg < 8; sg++) r += part[sg][tid];
        out[b * OUT_DIM + tid] = r;
    }
}

// ---------------------------------------------------------------------------
extern "C" void kernel_launch(void* const* d_in, const int* in_sizes, int n_in,
                              void* d_out, int out_size) {
    const float* x   = (const float*)d_in[0];
    const float* Wih = (const float*)d_in[1];
    const float* Whh = (const float*)d_in[2];
    const float* bh  = (const float*)d_in[3];
    const float* fcw = (const float*)d_in[4];
    const float* fcb = (const float*)d_in[5];
    float* out = (float*)d_out;

    // 0) bf16 hi/lo splits of W_ih^T and x
    prep_w_kernel<<<256, 256>>>(Wih);
    prep_x_kernel<<<131072, 256>>>(x);

    // 1) input projection GEMM on tensor cores (mma.sync) -> g_xp
    cudaFuncSetAttribute(gemm_xp_mma_kernel,
                         cudaFuncAttributeMaxDynamicSharedMemorySize, GSMEM);
    gemm_xp_mma_kernel<<<(BATCH * T_STEPS) / 128, 512, GSMEM>>>(bh);

    // 2) persistent batch-parallel recurrence (K-split, 512 threads)
    cudaFuncSetAttribute(rnn_recurrence_kernel,
                         cudaFuncAttributeMaxDynamicSharedMemorySize, RSMEM);
    rnn_recurrence_kernel<<<BATCH / 2, 512, RSMEM>>>(Whh);

    // 3) classifier head
    rnn_head_kernel<<<BATCH, 128>>>(fcw, fcb, out);
}

// round 8
// speedup vs baseline: 1.4209x; 1.4209x over previous
#include <cuda_runtime.h>
#include <cuda_bf16.h>
#include <math.h>
#include <stdint.h>

// Problem constants (fixed shapes)
#define T_STEPS 2048
#define BATCH   256
#define HID     256
#define OUT_DIM 16

// Scratch (device globals: allocation-free kernel_launch)
__device__ float g_xp[134217728];          // [T][B][H] fp32, 512 MB
__device__ float g_hfinal[BATCH * HID];
__device__ __nv_bfloat16 g_xhi[134217728]; // x hi split, 256 MB
__device__ __nv_bfloat16 g_xlo[134217728]; // x lo split, 256 MB
__device__ __nv_bfloat16 g_WThi[65536];    // W_ih^T hi: [n][k]
__device__ __nv_bfloat16 g_WTlo[65536];    // W_ih^T lo: [n][k]

// ---------------------------------------------------------------------------
// helpers
// ---------------------------------------------------------------------------
__device__ __forceinline__ uint32_t smem_u32(const void* p) {
    uint32_t a;
    asm("{ .reg .u64 t; cvta.to.shared.u64 t, %1; cvt.u32.u64 %0, t; }"
        : "=r"(a) : "l"(p));
    return a;
}
__device__ __forceinline__ void cp16(uint32_t dst, const void* src) {
    asm volatile("cp.async.cg.shared.global [%0], [%1], 16;"
                 :: "r"(dst), "l"(src) : "memory");
}
__device__ __forceinline__ void ldsm_x4(uint32_t* r, uint32_t addr) {
    asm volatile("ldmatrix.sync.aligned.m8n8.x4.shared.b16 {%0,%1,%2,%3}, [%4];"
                 : "=r"(r[0]), "=r"(r[1]), "=r"(r[2]), "=r"(r[3]) : "r"(addr));
}
__device__ __forceinline__ void ldsm_x2(uint32_t* r, uint32_t addr) {
    asm volatile("ldmatrix.sync.aligned.m8n8.x2.shared.b16 {%0,%1}, [%2];"
                 : "=r"(r[0]), "=r"(r[1]) : "r"(addr));
}
__device__ __forceinline__ void mma_bf16(float* c, const uint32_t* a, const uint32_t* b) {
    asm volatile(
        "mma.sync.aligned.m16n8k16.row.col.f32.bf16.bf16.f32 "
        "{%0,%1,%2,%3}, {%4,%5,%6,%7}, {%8,%9}, {%0,%1,%2,%3};"
        : "+f"(c[0]), "+f"(c[1]), "+f"(c[2]), "+f"(c[3])
        : "r"(a[0]), "r"(a[1]), "r"(a[2]), "r"(a[3]), "r"(b[0]), "r"(b[1]));
}

// f32x2 helpers (recurrence)
__device__ __forceinline__ unsigned long long f32x2_pack(float x, float y) {
    unsigned long long r;
    asm("mov.b64 %0, {%1, %2};" : "=l"(r) : "r"(__float_as_uint(x)), "r"(__float_as_uint(y)));
    return r;
}
__device__ __forceinline__ void f32x2_unpack(unsigned long long v, float& x, float& y) {
    unsigned int lo, hi;
    asm("mov.b64 {%0, %1}, %2;" : "=r"(lo), "=r"(hi) : "l"(v));
    x = __uint_as_float(lo);
    y = __uint_as_float(hi);
}
__device__ __forceinline__ void ffma2(unsigned long long& acc,
                                      unsigned long long a, unsigned long long b) {
    asm("fma.rn.f32x2 %0, %1, %2, %0;" : "+l"(acc) : "l"(a), "l"(b));
}
__device__ __forceinline__ void fadd2(unsigned long long& acc, unsigned long long b) {
    asm("add.rn.f32x2 %0, %0, %1;" : "+l"(acc) : "l"(b));
}

// ---------------------------------------------------------------------------
// Kernel 0a: W_ih [k][n] -> transposed bf16 hi/lo [n][k]
// ---------------------------------------------------------------------------
__global__ __launch_bounds__(256)
void prep_w_kernel(const float* __restrict__ Wih) {
    int n = blockIdx.x;
    int k = threadIdx.x;
    float w = Wih[k * 256 + n];
    __nv_bfloat16 hi = __float2bfloat16(w);
    float lof = w - __bfloat162float(hi);
    g_WThi[n * 256 + k] = hi;
    g_WTlo[n * 256 + k] = __float2bfloat16(lof);
}

// ---------------------------------------------------------------------------
// Kernel 0b: x fp32 -> bf16 hi/lo splits (streaming)
// ---------------------------------------------------------------------------
__global__ __launch_bounds__(256)
void prep_x_kernel(const float* __restrict__ x) {
    size_t i = ((size_t)blockIdx.x * 256 + threadIdx.x) * 4;
    float4 f = *(const float4*)&x[i];
    __nv_bfloat162 h0 = __float22bfloat162_rn(make_float2(f.x, f.y));
    __nv_bfloat162 h1 = __float22bfloat162_rn(make_float2(f.z, f.w));
    float2 l0 = make_float2(f.x - __bfloat162float(h0.x), f.y - __bfloat162float(h0.y));
    float2 l1 = make_float2(f.z - __bfloat162float(h1.x), f.w - __bfloat162float(h1.y));
    __nv_bfloat162 lo0 = __float22bfloat162_rn(l0);
    __nv_bfloat162 lo1 = __float22bfloat162_rn(l1);
    uint2 hv, lv;
    hv.x = *(uint32_t*)&h0; hv.y = *(uint32_t*)&h1;
    lv.x = *(uint32_t*)&lo0; lv.y = *(uint32_t*)&lo1;
    *(uint2*)&g_xhi[i] = hv;
    *(uint2*)&g_xlo[i] = lv;
}

// ---------------------------------------------------------------------------
// Kernel 1: mma.sync bf16-split GEMM (unchanged from R5 passing version)
// ---------------------------------------------------------------------------
#define PADROW   40
#define AHI_OFF  0
#define ALO_OFF  10240
#define BHI_OFF  20480
#define BLO_OFF  40960
#define STAGE_B  61440
#define GSMEM    (2 * STAGE_B)

__global__ __launch_bounds__(512, 1)
void gemm_xp_mma_kernel(const float* __restrict__ bh) {
    extern __shared__ __align__(16) char dsm[];
    __shared__ float bias_s[256];

    const int tid = threadIdx.x;
    const int wid = tid >> 5;
    const int lid = tid & 31;
    const int wm  = wid & 1;
    const int wn  = wid >> 1;
    const uint32_t sb = smem_u32(dsm);

    if (tid < 256) bias_s[tid] = bh[tid];

    const size_t r0 = (size_t)blockIdx.x * 128;

    auto fill = [&](int s, int kt) {
        uint32_t base = sb + s * STAGE_B;
        {
            int c = tid;
            int row = c >> 2, q = c & 3;
            size_t ga = (r0 + row) * 256 + kt + q * 8;
            uint32_t d = base + row * (PADROW * 2) + q * 16;
            cp16(d + AHI_OFF, g_xhi + ga);
            cp16(d + ALO_OFF, g_xlo + ga);
        }
#pragma unroll
        for (int i = 0; i < 2; i++) {
            int c = tid + i * 512;
            int row = c >> 2, q = c & 3;
            size_t gb = (size_t)row * 256 + kt + q * 8;
            uint32_t d = base + row * (PADROW * 2) + q * 16;
            cp16(d + BHI_OFF, g_WThi + gb);
            cp16(d + BLO_OFF, g_WTlo + gb);
        }
    };

    float acc[4][4][4];
#pragma unroll
    for (int mi = 0; mi < 4; mi++)
#pragma unroll
        for (int ni = 0; ni < 4; ni++)
#pragma unroll
            for (int e = 0; e < 4; e++) acc[mi][ni][e] = 0.f;

    fill(0, 0);
    asm volatile("cp.async.commit_group;" ::: "memory");
    fill(1, 32);
    asm volatile("cp.async.commit_group;" ::: "memory");

    const int arow  = wm * 64 + (lid & 15);
    const int acolb = (lid >> 4) * 16;
    const int bnrow = wn * 32 + (lid & 7);
    const int bkoff = ((lid >> 3) & 1) * 16;

    for (int it = 0; it < 8; it++) {
        asm volatile("cp.async.wait_group 1;" ::: "memory");
        __syncthreads();

        uint32_t As = sb + (it & 1) * STAGE_B;
        uint32_t Bs = As + BHI_OFF;

#pragma unroll
        for (int k16 = 0; k16 < 2; k16++) {
            uint32_t ahi[4][4], alo[4][4];
#pragma unroll
            for (int mi = 0; mi < 4; mi++) {
                uint32_t a = As + (arow + mi * 16) * (PADROW * 2) + k16 * 32 + acolb;
                ldsm_x4(ahi[mi], a + AHI_OFF);
                ldsm_x4(alo[mi], a + ALO_OFF);
            }
#pragma unroll
            for (int ni = 0; ni < 4; ni++) {
                uint32_t bhi[2], blo[2];
                uint32_t ba = Bs + (bnrow + ni * 8) * (PADROW * 2) + k16 * 32 + bkoff;
                ldsm_x2(bhi, ba);
                ldsm_x2(blo, ba + (BLO_OFF - BHI_OFF));
#pragma unroll
                for (int mi = 0; mi < 4; mi++) {
                    mma_bf16(acc[mi][ni], ahi[mi], bhi);
                    mma_bf16(acc[mi][ni], alo[mi], bhi);
                    mma_bf16(acc[mi][ni], ahi[mi], blo);
                }
            }
        }
        __syncthreads();
        if (it + 2 < 8) fill(it & 1, (it + 2) * 32);
        asm volatile("cp.async.commit_group;" ::: "memory");
    }

#pragma unroll
    for (int mi = 0; mi < 4; mi++) {
#pragma unroll
        for (int ni = 0; ni < 4; ni++) {
            int m = wm * 64 + mi * 16 + (lid >> 2);
            int n = wn * 32 + ni * 8 + (lid & 3) * 2;
            float b0 = bias_s[n], b1 = bias_s[n + 1];
            {
                size_t r = r0 + m;
                int t = (int)(r & 2047), b = (int)(r >> 11);
                float2 v = make_float2(acc[mi][ni][0] + b0, acc[mi][ni][1] + b1);
                *(float2*)&g_xp[((size_t)t * BATCH + b) * HID + n] = v;
            }
            {
                size_t r = r0 + m + 8;
                int t = (int)(r & 2047), b = (int)(r >> 11);
                float2 v = make_float2(acc[mi][ni][2] + b0, acc[mi][ni][3] + b1);
                *(float2*)&g_xp[((size_t)t * BATCH + b) * HID + n] = v;
            }
        }
    }
}

// ---------------------------------------------------------------------------
// Kernel 2: warp-uniform K-split recurrence.
// 128 CTAs x 256 threads (8 warps). Warps 0-3 = K-half 0 (k in [0,128)),
// warps 4-7 = K-half 1 (k in [128,256)). Thread idx = tid & 127 owns
// columns jA = idx and jB = idx + 128 over its 128-row K-range:
//   - rows [kbase, kbase+64)  : registers, u64 k-pairs (32 per column)
//   - rows [kbase+64, kbase+128): smem quads [group][j][4]
// h stored per-batch fp32[256] x 2; all h loads are single-address
// warp broadcasts (warp is K-half-uniform). Cross-half combine via smem
// float2 exchange; half0 finishes batch0, half1 finishes batch1 (symmetric).
// smem: W 32 groups * 4096 = 131072 | h 2*1024 @131072 | xbuf 2*1024 @133120
// ---------------------------------------------------------------------------
#define RH_OFF  131072
#define RX_OFF  133120
#define RSMEM   135168

__global__ __launch_bounds__(256, 1)
void rnn_recurrence_kernel(const float* __restrict__ W_hh) {
    extern __shared__ __align__(16) char sm[];

    const int tid  = threadIdx.x;
    const int half = tid >> 7;            // warps 0-3 -> 0, warps 4-7 -> 1
    const int idx  = tid & 127;
    const int jA   = idx;
    const int jB   = idx + 128;
    const int b0   = blockIdx.x * 2;
    const int kbase = half * 128;

    // --- fill W smem: group g = h*16 + q -> rows h*128 + 64 + 4q .. +3 ---
    for (int e = tid; e < 32 * 256; e += 256) {
        int g = e >> 8;
        int j = e & 255;
        int h = g >> 4, q = g & 15;
        int row = h * 128 + 64 + 4 * q;
        float4 v;
        v.x = W_hh[(row + 0) * 256 + j];
        v.y = W_hh[(row + 1) * 256 + j];
        v.z = W_hh[(row + 2) * 256 + j];
        v.w = W_hh[(row + 3) * 256 + j];
        *(float4*)(sm + g * 4096 + j * 16) = v;
    }

    // --- W register rows [kbase, kbase+64) for columns jA, jB (u64 k-pairs) ---
    unsigned long long wA[32], wB[32];
#pragma unroll
    for (int r = 0; r < 32; r++) {
        wA[r] = f32x2_pack(W_hh[(kbase + 2 * r) * 256 + jA],
                           W_hh[(kbase + 2 * r + 1) * 256 + jA]);
        wB[r] = f32x2_pack(W_hh[(kbase + 2 * r) * 256 + jB],
                           W_hh[(kbase + 2 * r + 1) * 256 + jB]);
    }

    // --- zero h[2][256] ---
    ((float*)(sm + RH_OFF))[tid] = 0.f;
    ((float*)(sm + RH_OFF))[tid + 256] = 0.f;
    __syncthreads();

    // xp for finish batch (= b0 + half), columns jA and jB
    const float* xpA = g_xp + (size_t)(b0 + half) * HID + jA;
    float pA = xpA[0];
    float pB = xpA[128];

    const char* hb0 = sm + RH_OFF + kbase * 4;          // h[b0], my k segment
    const char* hb1 = sm + RH_OFF + 1024 + kbase * 4;   // h[b1], my k segment
    const char* wsm = sm + half * 16 * 4096;            // my half's smem groups

    float hA = 0.f, hB = 0.f;

    for (int t = 0; t < T_STEPS; t++) {
        // 8 accumulator chains: (col A/B) x (batch 0/1) x (2 k-pair lanes)
        unsigned long long aA0x = 0, aA0y = 0, aA1x = 0, aA1y = 0;
        unsigned long long aB0x = 0, aB0y = 0, aB1x = 0, aB1y = 0;

        int tn = (t + 1 < T_STEPS) ? (t + 1) : t;
        float pAn = xpA[(size_t)tn * (BATCH * HID)];
        float pBn = xpA[(size_t)tn * (BATCH * HID) + 128];

        // register-W part: k-local [0,64), 16 h-quads
#pragma unroll
        for (int q = 0; q < 16; q++) {
            ulonglong2 h0 = *(const ulonglong2*)(hb0 + q * 16);
            ulonglong2 h1 = *(const ulonglong2*)(hb1 + q * 16);
            ffma2(aA0x, h0.x, wA[2 * q]);
            ffma2(aA0y, h0.y, wA[2 * q + 1]);
            ffma2(aA1x, h1.x, wA[2 * q]);
            ffma2(aA1y, h1.y, wA[2 * q + 1]);
            ffma2(aB0x, h0.x, wB[2 * q]);
            ffma2(aB0y, h0.y, wB[2 * q + 1]);
            ffma2(aB1x, h1.x, wB[2 * q]);
            ffma2(aB1y, h1.y, wB[2 * q + 1]);
        }
        // smem-W part: k-local [64,128), 16 h-quads
#pragma unroll
        for (int q = 0; q < 16; q++) {
            ulonglong2 wqA = *(const ulonglong2*)(wsm + q * 4096 + jA * 16);
            ulonglong2 wqB = *(const ulonglong2*)(wsm + q * 4096 + jB * 16);
            ulonglong2 h0  = *(const ulonglong2*)(hb0 + 256 + q * 16);
            ulonglong2 h1  = *(const ulonglong2*)(hb1 + 256 + q * 16);
            ffma2(aA0x, h0.x, wqA.x);
            ffma2(aA0y, h0.y, wqA.y);
            ffma2(aA1x, h1.x, wqA.x);
            ffma2(aA1y, h1.y, wqA.y);
            ffma2(aB0x, h0.x, wqB.x);
            ffma2(aB0y, h0.y, wqB.y);
            ffma2(aB1x, h1.x, wqB.x);
            ffma2(aB1y, h1.y, wqB.y);
        }

        // collapse chains -> 4 partial scalars: (colA,b0) (colA,b1) (colB,b0) (colB,b1)
        fadd2(aA0x, aA0y);
        fadd2(aA1x, aA1y);
        fadd2(aB0x, aB0y);
        fadd2(aB1x, aB1y);
        float lo, hi;
        f32x2_unpack(aA0x, lo, hi); float sA0 = lo + hi;
        f32x2_unpack(aA1x, lo, hi); float sA1 = lo + hi;
        f32x2_unpack(aB0x, lo, hi); float sB0 = lo + hi;
        f32x2_unpack(aB1x, lo, hi); float sB1 = lo + hi;

        // exchange: each half publishes the OTHER batch's partials
        float2* xb = (float2*)(sm + RX_OFF + half * 1024) + idx;
        *xb = (half == 0) ? make_float2(sA1, sB1) : make_float2(sA0, sB0);
        __syncthreads();
        float2 other = *((const float2*)(sm + RX_OFF + (half ^ 1) * 1024) + idx);
        float totA = ((half == 0) ? sA0 : sA1) + other.x + pA;
        float totB = ((half == 0) ? sB0 : sB1) + other.y + pB;
        hA = tanhf(totA);
        hB = tanhf(totB);
        pA = pAn;
        pB = pBn;
        // publish h for my batch (in place: all k-loop reads finished at barrier)
        float* hrow = (float*)(sm + RH_OFF + half * 1024);
        hrow[jA] = hA;
        hrow[jB] = hB;
        __syncthreads();
    }

    g_hfinal[(size_t)(b0 + half) * HID + jA] = hA;
    g_hfinal[(size_t)(b0 + half) * HID + jB] = hB;
}

// ---------------------------------------------------------------------------
// Kernel 3: classifier head (tiny)
// ---------------------------------------------------------------------------
__global__ __launch_bounds__(128)
void rnn_head_kernel(const float* __restrict__ fcw,
                     const float* __restrict__ fcb,
                     float* __restrict__ out) {
    __shared__ float hs[HID];
    __shared__ float part[8][OUT_DIM];
    const int b = blockIdx.x;
    const int tid = threadIdx.x;

    hs[tid]       = g_hfinal[(size_t)b * HID + tid];
    hs[tid + 128] = g_hfinal[(size_t)b * HID + tid + 128];
    __syncthreads();

    const int o   = tid & 15;
    const int seg = tid >> 4;
    float s = 0.f;
#pragma unroll
    for (int jj = 0; jj < 32; jj++) {
        int j = seg * 32 + jj;
        s += hs[j] * fcw[o * HID + j];
    }
    part[seg][o] = s;
    __syncthreads();
    if (tid < OUT_DIM) {
        float r = fcb[tid];
#pragma unroll
        for (int sg = 0; sg < 8; sg++) r += part[sg][tid];
        out[b * OUT_DIM + tid] = r;
    }
}

// ---------------------------------------------------------------------------
extern "C" void kernel_launch(void* const* d_in, const int* in_sizes, int n_in,
                              void* d_out, int out_size) {
    const float* x   = (const float*)d_in[0];
    const float* Wih = (const float*)d_in[1];
    const float* Whh = (const float*)d_in[2];
    const float* bh  = (const float*)d_in[3];
    const float* fcw = (const float*)d_in[4];
    const float* fcb = (const float*)d_in[5];
    float* out = (float*)d_out;

    // 0) bf16 hi/lo splits of W_ih^T and x
    prep_w_kernel<<<256, 256>>>(Wih);
    prep_x_kernel<<<131072, 256>>>(x);

    // 1) input projection GEMM on tensor cores (mma.sync) -> g_xp
    cudaFuncSetAttribute(gemm_xp_mma_kernel,
                         cudaFuncAttributeMaxDynamicSharedMemorySize, GSMEM);
    gemm_xp_mma_kernel<<<(BATCH * T_STEPS) / 128, 512, GSMEM>>>(bh);

    // 2) persistent recurrence (warp-uniform K-split, 2 cols/thread)
    cudaFuncSetAttribute(rnn_recurrence_kernel,
                         cudaFuncAttributeMaxDynamicSharedMemorySize, RSMEM);
    rnn_recurrence_kernel<<<BATCH / 2, 256, RSMEM>>>(Whh);

    // 3) classifier head
    rnn_head_kernel<<<BATCH, 128>>>(fcw, fcb, out);
}